// round 15
// baseline (speedup 1.0000x reference)
#include <cuda_runtime.h>
#include <cuda_fp16.h>
#include <cuda_bf16.h>

#define SQ 1024
#define NB 8
#define NE 512
#define NH 8
#define QHD 32
#define PHD 4
#define PDIM 192
#define NPOS (2*SQ-1)   // 2047
#define INPROJ 544
#define MROWS (SQ*NB)   // 8192
#define K2E (NE/2)      // 256
#define LOG2E 1.4426950408889634f

typedef unsigned long long u64;
typedef unsigned int u32;

// bf16 mma m16n8k16, fp32 accumulate (in-place)
#define MMA16816(d, a0, a1, a2, a3, b0, b1) \
    asm("mma.sync.aligned.m16n8k16.row.col.f32.bf16.bf16.f32 " \
        "{%0,%1,%2,%3}, {%4,%5,%6,%7}, {%8,%9}, {%0,%1,%2,%3};" \
        : "+f"(d[0]), "+f"(d[1]), "+f"(d[2]), "+f"(d[3]) \
        : "r"(a0), "r"(a1), "r"(a2), "r"(a3), "r"(b0), "r"(b1))

#define CPA16(d, s) asm volatile("cp.async.cg.shared.global [%0], [%1], 16;" :: "r"(d), "l"(s))
#define CPA4(d, s)  asm volatile("cp.async.ca.shared.global [%0], [%1], 4;"  :: "r"(d), "l"(s))
#define CPA_COMMIT() asm volatile("cp.async.commit_group;")
#define CPA_WAITG1() asm volatile("cp.async.wait_group 1;" ::: "memory")

__device__ __forceinline__ float fast_exp2(float x)
{
    float r;
    asm("ex2.approx.f32 %0, %1;" : "=f"(r) : "f"(x));
    return r;
}

// Scratch (device globals; no allocations allowed)
__device__ __align__(16) u32  g_xh[MROWS*K2E];     // x split hi [row][k2]
__device__ __align__(16) u32  g_xl[MROWS*K2E];
__device__ __align__(16) u32  g_whT[K2E*INPROJ];   // w split hi, transposed [k2][col]
__device__ __align__(16) u32  g_wlT[K2E*INPROJ];
__device__ __align__(16) u32  g_qh[NH*NB*SQ*16];   // [hb][s][perm(d2)] bf16x2 hi (scaled log2e)
__device__ __align__(16) u32  g_ql[NH*NB*SQ*16];
__device__ __align__(16) u32  g_kh[NH*NB*SQ*16];   // [hb][s][d2] (UNPERMUTED)
__device__ __align__(16) u32  g_kl[NH*NB*SQ*16];
__device__ __align__(16) float g_p[NH*NB*SQ*PHD];  // [hb][s][d] fp32 (scaled log2e)
__device__ __align__(16) float4 g_pe_f[NH*NPOS + 8]; // [h][n]: 4 x fp32

// v0,v1 -> hi (bf16x2: lo-half=v0), lo = residual pair
__device__ __forceinline__ void split_pair(float c0, float c1, u32& hi, u32& lo)
{
    u32 h;
    asm("cvt.rn.bf16x2.f32 %0, %1, %2;" : "=r"(h) : "f"(c1), "f"(c0));
    float f0 = __uint_as_float(h << 16);
    float f1 = __uint_as_float(h & 0xffff0000u);
    float r0 = c0 - f0, r1 = c1 - f1;
    asm("cvt.rn.bf16x2.f32 %0, %1, %2;" : "=r"(lo) : "f"(r1), "f"(r0));
    hi = h;
}

// ---------------------------------------------------------------------------
// Kernel 0 (merged): blocks [0, SPLIT_BLOCKS) split x/w into bf16 hi/lo;
// blocks [SPLIT_BLOCKS, +64) compute pe projection (fp32x4).
// ---------------------------------------------------------------------------
#define XTOT (MROWS*K2E)
#define WTOT (INPROJ*K2E)
#define SPLIT_BLOCKS ((XTOT + WTOT + 255)/256)   // 8704 + ...
#define PE_BLOCKS (8*NH)                          // 8 n-blocks x 8 heads

__global__ __launch_bounds__(256) void prep_kernel(
    const float* __restrict__ x, const float* __restrict__ w,
    const float* __restrict__ pos_emb, const float* __restrict__ lw)
{
    const int blk = blockIdx.x;
    const int tid = threadIdx.x;
    if (blk < SPLIT_BLOCKS) {
        int idx = blk * 256 + tid;
        if (idx < XTOT) {
            int row = idx >> 8, k2 = idx & 255;
            float2 v = *(const float2*)&x[(size_t)row*NE + 2*k2];
            u32 hi, lo; split_pair(v.x, v.y, hi, lo);
            g_xh[idx] = hi; g_xl[idx] = lo;
        } else {
            int i = idx - XTOT;
            if (i < WTOT) {
                int k2 = i / INPROJ, col = i % INPROJ;
                float2 v = *(const float2*)&w[(size_t)col*NE + 2*k2];
                u32 hi, lo; split_pair(v.x, v.y, hi, lo);
                g_whT[(size_t)k2*INPROJ + col] = hi;
                g_wlT[(size_t)k2*INPROJ + col] = lo;
            }
        }
        return;
    }
    // ---- pe path ----
    __shared__ float ws[4][193];
    const int pb = blk - SPLIT_BLOCKS;
    const int h = pb & 7;
    const int nblk = pb >> 3;
    for (int i = tid; i < 4*PDIM; i += 256) {
        int o = i / PDIM, p = i % PDIM;
        ws[o][p] = lw[(h*4+o)*PDIM + p];
    }
    __syncthreads();
    int n = nblk * 256 + tid;
    if (n >= NPOS) return;
    float a0 = 0.f, a1 = 0.f, a2 = 0.f, a3 = 0.f;
    const float4* pr = (const float4*)&pos_emb[(size_t)n*PDIM];
#pragma unroll 4
    for (int p4 = 0; p4 < PDIM/4; ++p4) {
        float4 pv = __ldg(&pr[p4]);
        int p = p4*4;
        a0 = fmaf(pv.x, ws[0][p+0], a0); a1 = fmaf(pv.x, ws[1][p+0], a1);
        a2 = fmaf(pv.x, ws[2][p+0], a2); a3 = fmaf(pv.x, ws[3][p+0], a3);
        a0 = fmaf(pv.y, ws[0][p+1], a0); a1 = fmaf(pv.y, ws[1][p+1], a1);
        a2 = fmaf(pv.y, ws[2][p+1], a2); a3 = fmaf(pv.y, ws[3][p+1], a3);
        a0 = fmaf(pv.z, ws[0][p+2], a0); a1 = fmaf(pv.z, ws[1][p+2], a1);
        a2 = fmaf(pv.z, ws[2][p+2], a2); a3 = fmaf(pv.z, ws[3][p+2], a3);
        a0 = fmaf(pv.w, ws[0][p+3], a0); a1 = fmaf(pv.w, ws[1][p+3], a1);
        a2 = fmaf(pv.w, ws[2][p+3], a2); a3 = fmaf(pv.w, ws[3][p+3], a3);
    }
    g_pe_f[h*NPOS + n] = make_float4(a0, a1, a2, a3);
}

// ---------------------------------------------------------------------------
// Kernel 1: proj = x @ W^T + b via split-bf16 mma.sync (hh+hl+lh).
// q epilogue writes PERMUTED d2 position; k UNPERMUTED; q,p scaled by log2e.
// ---------------------------------------------------------------------------
#define PA 20
#define PB 72
#define ST_A  2560
#define ST_B  1152
#define ST_SZ (2*ST_A + 2*ST_B)
#define SMEM_PROJ (2*ST_SZ*4)

__global__ __launch_bounds__(256, 2) void proj_mma_kernel(
    const float* __restrict__ bias)
{
    extern __shared__ u32 sm[];
    const int tid = threadIdx.x;
    const int w = tid >> 5, lane = tid & 31;
    const int g = lane >> 2, tig = lane & 3;
    const int warp_m = w >> 1, warp_n = w & 1;
    const int m0 = blockIdx.y * 128;
    const int n0 = blockIdx.x * 64;

    const int a_row = tid >> 1, a_half = tid & 1;
    const uint4* xh4 = (const uint4*)g_xh;
    const uint4* xl4 = (const uint4*)g_xl;
    const size_t a_base = ((size_t)(m0 + a_row)*K2E) >> 2;

    const int b_k2l = tid >> 4, b_colq = tid & 15;
    const bool b_valid = (n0 + b_colq*4) < INPROJ;

    uint4 pa_h0, pa_h1, pa_l0, pa_l1, pb_h, pb_l;
    {
        size_t ai = a_base + a_half*2;
        pa_h0 = __ldg(&xh4[ai]);   pa_h1 = __ldg(&xh4[ai+1]);
        pa_l0 = __ldg(&xl4[ai]);   pa_l1 = __ldg(&xl4[ai+1]);
        if (b_valid) {
            size_t bi = ((size_t)b_k2l*INPROJ + n0 + b_colq*4) >> 2;
            pb_h = __ldg(&((const uint4*)g_whT)[bi]);
            pb_l = __ldg(&((const uint4*)g_wlT)[bi]);
        } else {
            pb_h = make_uint4(0,0,0,0); pb_l = pb_h;
        }
    }

    float acc[2][4][4];
#pragma unroll
    for (int mt = 0; mt < 2; ++mt)
#pragma unroll
        for (int nt = 0; nt < 4; ++nt)
#pragma unroll
            for (int i = 0; i < 4; ++i) acc[mt][nt][i] = 0.f;

    for (int kc = 0; kc < 16; ++kc) {
        const int s = kc & 1;
        u32* Ah = sm + s*ST_SZ;
        u32* Al = Ah + ST_A;
        u32* Bh = Al + ST_A;
        u32* Bl = Bh + ST_B;
        *(uint4*)&Ah[a_row*PA + a_half*8]     = pa_h0;
        *(uint4*)&Ah[a_row*PA + a_half*8 + 4] = pa_h1;
        *(uint4*)&Al[a_row*PA + a_half*8]     = pa_l0;
        *(uint4*)&Al[a_row*PA + a_half*8 + 4] = pa_l1;
        *(uint4*)&Bh[b_k2l*PB + b_colq*4] = pb_h;
        *(uint4*)&Bl[b_k2l*PB + b_colq*4] = pb_l;
        __syncthreads();
        if (kc < 15) {
            size_t ai = a_base + (kc+1)*4 + a_half*2;
            pa_h0 = __ldg(&xh4[ai]);   pa_h1 = __ldg(&xh4[ai+1]);
            pa_l0 = __ldg(&xl4[ai]);   pa_l1 = __ldg(&xl4[ai+1]);
            if (b_valid) {
                size_t bi = ((size_t)((kc+1)*16 + b_k2l)*INPROJ + n0 + b_colq*4) >> 2;
                pb_h = __ldg(&((const uint4*)g_whT)[bi]);
                pb_l = __ldg(&((const uint4*)g_wlT)[bi]);
            }
        }
#pragma unroll
        for (int ks = 0; ks < 2; ++ks) {
            const int kb = ks*8;
            u32 ah[2][4], al[2][4];
#pragma unroll
            for (int mt = 0; mt < 2; ++mt) {
                int r1 = (warp_m*32 + mt*16 + g) * PA;
                int r2 = r1 + 8*PA;
                ah[mt][0] = Ah[r1 + kb + tig];
                ah[mt][1] = Ah[r2 + kb + tig];
                ah[mt][2] = Ah[r1 + kb + 4 + tig];
                ah[mt][3] = Ah[r2 + kb + 4 + tig];
                al[mt][0] = Al[r1 + kb + tig];
                al[mt][1] = Al[r2 + kb + tig];
                al[mt][2] = Al[r1 + kb + 4 + tig];
                al[mt][3] = Al[r2 + kb + 4 + tig];
            }
#pragma unroll
            for (int nt = 0; nt < 4; ++nt) {
                int col = warp_n*32 + nt*8 + g;
                u32 bh0 = Bh[(kb + tig)*PB + col];
                u32 bh1 = Bh[(kb + 4 + tig)*PB + col];
                u32 bl0 = Bl[(kb + tig)*PB + col];
                u32 bl1 = Bl[(kb + 4 + tig)*PB + col];
#pragma unroll
                for (int mt = 0; mt < 2; ++mt) {
                    MMA16816(acc[mt][nt], ah[mt][0], ah[mt][1], ah[mt][2], ah[mt][3], bh0, bh1);
                    MMA16816(acc[mt][nt], ah[mt][0], ah[mt][1], ah[mt][2], ah[mt][3], bl0, bl1);
                    MMA16816(acc[mt][nt], al[mt][0], al[mt][1], al[mt][2], al[mt][3], bh0, bh1);
                }
            }
        }
        __syncthreads();
    }

#pragma unroll
    for (int nt = 0; nt < 4; ++nt) {
        const int n = n0 + warp_n*32 + nt*8 + 2*tig;
        if (n >= INPROJ) continue;
        const float b0 = __ldg(&bias[n]);
        const float b1 = __ldg(&bias[n+1]);
#pragma unroll
        for (int mt = 0; mt < 2; ++mt) {
#pragma unroll
            for (int rr = 0; rr < 2; ++rr) {
                const int m = m0 + warp_m*32 + mt*16 + g + rr*8;
                const int srow = m >> 3, bb = m & 7;
                float c0 = acc[mt][nt][2*rr]     + b0;
                float c1 = acc[mt][nt][2*rr + 1] + b1;
                if (n < 512) {
                    int nn = n & 255;
                    int h = nn >> 5, d2 = (nn & 31) >> 1;
                    u32 hi, lo;
                    if (n < 256) {
                        c0 *= LOG2E; c1 *= LOG2E;
                        split_pair(c0, c1, hi, lo);
                        int pos = (d2 & 3)*4 + (d2 >> 2);   // permuted (q only)
                        size_t off = (((size_t)(h*8+bb))*SQ + srow)*16 + pos;
                        g_qh[off] = hi; g_ql[off] = lo;
                    } else {
                        split_pair(c0, c1, hi, lo);
                        size_t off = (((size_t)(h*8+bb))*SQ + srow)*16 + d2;  // unpermuted
                        g_kh[off] = hi; g_kl[off] = lo;
                    }
                } else {
                    int n3 = n - 512;
                    int h = n3 >> 2, d = n3 & 3;
                    size_t off = (((size_t)(h*8+bb))*SQ + srow)*PHD + d;
                    g_p[off]   = c0 * LOG2E;
                    g_p[off+1] = c1 * LOG2E;
                }
            }
        }
    }
}

// ---------------------------------------------------------------------------
// Kernel 2: persistent attention. Grid (2, 64) = 128 CTAs, one per SM.
// K resident (scalar B-frags, [j][d2] pitch 20); pe fp32 double-buffered;
// mask hoisted to register bitmask; epilogue FFMA-seeded + ex2.
// ---------------------------------------------------------------------------
#define KJ_P 20
#define OFF_KB   0                          // 2 * 1024*20*4 = 163840
#define KB_LO    (1024*KJ_P)                // u32 offset of lo array
#define OFF_PE0  163840                     // 8 pairs * 160 float4 = 20480
#define OFF_PE1  184320                     // 20480
#define OFF_RED  204800                     // 32*8*4 = 1024
#define OFF_INV  205824                     // 128
#define OFF_MASK 205952                     // 8 pairs * 128 = 1024
#define SMEM_ATTN 206976

struct BFrag { u32 h0, h1, h2, h3, l0, l1, l2, l3; };

__device__ __forceinline__ void ld_bfrag(BFrag& f, const u32* kb2h, const u32* kb2l,
                                         int jc, int tig)
{
    const u32* kr = kb2h + jc*KJ_P;
    const u32* lr = kb2l + jc*KJ_P;
    f.h0 = kr[tig];     f.h1 = kr[4 + tig];
    f.h2 = kr[8 + tig]; f.h3 = kr[12 + tig];
    f.l0 = lr[tig];     f.l1 = lr[4 + tig];
    f.l2 = lr[8 + tig]; f.l3 = lr[12 + tig];
}

__device__ __forceinline__ float dot4acc(float4 p, float4 e, float a)
{
    return fmaf(p.x, e.x, fmaf(p.y, e.y, fmaf(p.z, e.z, fmaf(p.w, e.w, a))));
}

__global__ __launch_bounds__(512, 1) void attn_kernel(
    const unsigned char* __restrict__ kpm, float* __restrict__ out)
{
    extern __shared__ char smraw[];
    u32*   kb2h  = (u32*)(smraw + OFF_KB);       // [1024 j][20] (16 k2 used)
    u32*   kb2l  = kb2h + KB_LO;
    float* red_s = (float*)(smraw + OFF_RED);    // [32][8]
    float* inv_s = (float*)(smraw + OFF_INV);    // [32]
    unsigned char* mask_l = (unsigned char*)(smraw + OFF_MASK); // [8][128]
    const u32 smb = (u32)__cvta_generic_to_shared(smraw);

    const int tid = threadIdx.x;
    const int w = tid >> 5, lane = tid & 31;
    const int g = lane >> 2, tig = lane & 3;
    const int pairid = w >> 1;
    const int jstart = pairid * 128;
    const int hb = blockIdx.y;
    const int h = hb >> 3, b = hb & 7;
    const int qbase = blockIdx.x * 512;
    const size_t hbSQ = (size_t)hb * SQ;
    const int tpair = (w & 1)*32 + lane;

    const int rbase = (w & 1) * 16;
    const int r1 = rbase + g, r2 = r1 + 8;

    // ---- prologue: K panel (once), mask (once), pe(0) ----
    {
        const u32* ksrc = ((w & 1) ? g_kl : g_kh) + (hbSQ + jstart)*16;
        const u32 kdst = smb + OFF_KB + (w & 1)*(KB_LO*4) + jstart*KJ_P*4;
#pragma unroll
        for (int i = 0; i < 16; ++i) {
            int lin = i*32 + lane;
            int jl = lin >> 2, seg = lin & 3;
            CPA16(kdst + (jl*KJ_P + seg*4)*4, ksrc + jl*16 + seg*4);
        }
        if (tpair < 32)
            CPA4(smb + OFF_MASK + pairid*128 + tpair*4,
                 kpm + (size_t)b*SQ + jstart + tpair*4);
        const float4* pesrc = g_pe_f + h*NPOS + (992 - qbase) + jstart;
        const u32 pedst = smb + OFF_PE0 + pairid*160*16;
#pragma unroll
        for (int it = 0; it < 3; ++it) {
            int i = tpair + it*64;
            if (i < 160) CPA16(pedst + i*16, pesrc + i);
        }
        CPA_COMMIT();
    }

    // A(0)/p(0) prefetch (register, per-warp)
    u32 ah[8], al[8];
    float4 pv1, pv2;
    {
        const uint4* qa = (const uint4*)(g_qh + (hbSQ + qbase + r1)*16);
        const uint4* qb = (const uint4*)(g_qh + (hbSQ + qbase + r2)*16);
        const uint4* la = (const uint4*)(g_ql + (hbSQ + qbase + r1)*16);
        const uint4* lb = (const uint4*)(g_ql + (hbSQ + qbase + r2)*16);
        uint4 v1 = __ldg(&qa[tig]);
        uint4 v2 = __ldg(&qb[tig]);
        uint4 u1 = __ldg(&la[tig]);
        uint4 u2 = __ldg(&lb[tig]);
        ah[0] = v1.x; ah[1] = v2.x; ah[2] = v1.y; ah[3] = v2.y;
        ah[4] = v1.z; ah[5] = v2.z; ah[6] = v1.w; ah[7] = v2.w;
        al[0] = u1.x; al[1] = u2.x; al[2] = u1.y; al[3] = u2.y;
        al[4] = u1.z; al[5] = u2.z; al[6] = u1.w; al[7] = u2.w;
        pv1 = *(const float4*)(g_p + (hbSQ + qbase + r1)*PHD);
        pv2 = *(const float4*)(g_p + (hbSQ + qbase + r2)*PHD);
    }

    // ---- hoist mask into a register bitmask (qi-invariant) ----
    u32 mbits = 0;
    {
        const unsigned char* mkb = mask_l + pairid*128;
        asm volatile("cp.async.wait_group 0;" ::: "memory");
        asm volatile("bar.sync %0, 64;" :: "r"(1 + pairid) : "memory");
#pragma unroll
        for (int t = 0; t < 16; ++t) {
            if (mkb[8*t + 2*tig])     mbits |= (1u << (2*t));
            if (mkb[8*t + 2*tig + 1]) mbits |= (1u << (2*t + 1));
        }
    }

#pragma unroll 1
    for (int qi = 0; qi < 16; ++qi) {
        const int q0 = qbase + qi*32;
        // issue pe(qi+1) into stage (qi+1)&1
        if (qi < 15) {
            const float4* pesrc = g_pe_f + h*NPOS + (992 - (q0 + 32)) + jstart;
            const u32 pedst = smb + (((qi+1) & 1) ? OFF_PE1 : OFF_PE0) + pairid*160*16;
#pragma unroll
            for (int it = 0; it < 3; ++it) {
                int i = tpair + it*64;
                if (i < 160) CPA16(pedst + i*16, pesrc + i);
            }
        }
        CPA_COMMIT();
        CPA_WAITG1();              // pe(qi) complete
        asm volatile("bar.sync %0, 64;" :: "r"(1 + pairid) : "memory");

        const float4* peb4 = (const float4*)(smraw + ((qi & 1) ? OFF_PE1 : OFF_PE0))
                             + pairid*160;

        float acc[16][4];
#pragma unroll
        for (int t = 0; t < 16; ++t)
#pragma unroll
            for (int i = 0; i < 4; ++i) acc[t][i] = 0.f;

        float s1 = 0.f, s2 = 0.f;

        // pe carry init (row2 of tile e uses row1 loads of tile e-1)
        const int idx0 = 2*tig + 31 - r1;     // idx1 at e=0; >= 8 always
        float4 c11 = peb4[idx0 - 8];
        float4 c12 = peb4[idx0 - 7];

        // ---- fused pipelined loop: MMA(t) overlaps epilogue(t-1) ----
        BFrag bf;
        ld_bfrag(bf, kb2h, kb2l, jstart + g, tig);
#pragma unroll
        for (int t = 0; t < 16; ++t) {
            BFrag cur = bf;
            if (t < 15) ld_bfrag(bf, kb2h, kb2l, jstart + 8*(t+1) + g, tig);
            MMA16816(acc[t], ah[0], ah[1], ah[2], ah[3], cur.h0, cur.h1);
            MMA16816(acc[t], ah[4], ah[5], ah[6], ah[7], cur.h2, cur.h3);
            MMA16816(acc[t], ah[0], ah[1], ah[2], ah[3], cur.l0, cur.l1);
            MMA16816(acc[t], ah[4], ah[5], ah[6], ah[7], cur.l2, cur.l3);
            MMA16816(acc[t], al[0], al[1], al[2], al[3], cur.h0, cur.h1);
            MMA16816(acc[t], al[4], al[5], al[6], al[7], cur.h2, cur.h3);

            if (t > 0) {
                const int e = t - 1;
                const int idx1 = 8*e + 2*tig + 31 - r1;
                float4 e11 = peb4[idx1];
                float4 e12 = peb4[idx1 + 1];
                const bool m0 = (mbits >> (2*e)) & 1;
                const bool m1 = (mbits >> (2*e + 1)) & 1;
                float e0 = m0 ? 0.f : fast_exp2(dot4acc(pv1, e11, acc[e][0]));
                float e1 = m1 ? 0.f : fast_exp2(dot4acc(pv1, e12, acc[e][1]));
                float e2 = m0 ? 0.f : fast_exp2(dot4acc(pv2, c11, acc[e][2]));
                float e3 = m1 ? 0.f : fast_exp2(dot4acc(pv2, c12, acc[e][3]));
                c11 = e11; c12 = e12;
                acc[e][0] = e0; acc[e][1] = e1; acc[e][2] = e2; acc[e][3] = e3;
                s1 += e0 + e1;
                s2 += e2 + e3;
            }
        }

        // ---- prefetch A/p for qi+1 (hidden behind tail+reduction+stores) ----
        if (qi < 15) {
            const int q0n = q0 + 32;
            const uint4* qa = (const uint4*)(g_qh + (hbSQ + q0n + r1)*16);
            const uint4* qb = (const uint4*)(g_qh + (hbSQ + q0n + r2)*16);
            const uint4* la = (const uint4*)(g_ql + (hbSQ + q0n + r1)*16);
            const uint4* lb = (const uint4*)(g_ql + (hbSQ + q0n + r2)*16);
            uint4 v1 = __ldg(&qa[tig]);
            uint4 v2 = __ldg(&qb[tig]);
            uint4 u1 = __ldg(&la[tig]);
            uint4 u2 = __ldg(&lb[tig]);
            ah[0] = v1.x; ah[1] = v2.x; ah[2] = v1.y; ah[3] = v2.y;
            ah[4] = v1.z; ah[5] = v2.z; ah[6] = v1.w; ah[7] = v2.w;
            al[0] = u1.x; al[1] = u2.x; al[2] = u1.y; al[3] = u2.y;
            al[4] = u1.z; al[5] = u2.z; al[6] = u1.w; al[7] = u2.w;
        }

        {   // epilogue tile 15
            const int e = 15;
            const int idx1 = 8*e + 2*tig + 31 - r1;
            float4 e11 = peb4[idx1];
            float4 e12 = peb4[idx1 + 1];
            const bool m0 = (mbits >> (2*e)) & 1;
            const bool m1 = (mbits >> (2*e + 1)) & 1;
            float e0 = m0 ? 0.f : fast_exp2(dot4acc(pv1, e11, acc[e][0]));
            float e1 = m1 ? 0.f : fast_exp2(dot4acc(pv1, e12, acc[e][1]));
            float e2 = m0 ? 0.f : fast_exp2(dot4acc(pv2, c11, acc[e][2]));
            float e3 = m1 ? 0.f : fast_exp2(dot4acc(pv2, c12, acc[e][3]));
            acc[e][0] = e0; acc[e][1] = e1; acc[e][2] = e2; acc[e][3] = e3;
            s1 += e0 + e1;
            s2 += e2 + e3;
        }

        if (qi < 15) {
            const int q0n = q0 + 32;
            pv1 = *(const float4*)(g_p + (hbSQ + q0n + r1)*PHD);
            pv2 = *(const float4*)(g_p + (hbSQ + q0n + r2)*PHD);
        }

        s1 += __shfl_xor_sync(0xffffffffu, s1, 1);
        s1 += __shfl_xor_sync(0xffffffffu, s1, 2);
        s2 += __shfl_xor_sync(0xffffffffu, s2, 1);
        s2 += __shfl_xor_sync(0xffffffffu, s2, 2);
        if (tig == 0) {
            red_s[r1*8 + pairid] = s1;
            red_s[r2*8 + pairid] = s2;
        }
        __syncthreads();
        if (tid < 32) {
            float s = red_s[tid*8];
#pragma unroll
            for (int i = 1; i < 8; ++i) s += red_s[tid*8 + i];
            inv_s[tid] = 1.0f / s;
        }
        __syncthreads();

        // ---- normalize + streaming float2 stores ----
        const float i1 = inv_s[r1], i2 = inv_s[r2];
        float2* o1 = (float2*)(out + (hbSQ + q0 + r1)*SQ);
        float2* o2 = (float2*)(out + (hbSQ + q0 + r2)*SQ);
#pragma unroll
        for (int t = 0; t < 16; ++t) {
            const int jp = (jstart + 8*t + 2*tig) >> 1;
            float2 v1 = make_float2(acc[t][0] * i1, acc[t][1] * i1);
            float2 v2 = make_float2(acc[t][2] * i2, acc[t][3] * i2);
            __stcs(&o1[jp], v1);
            __stcs(&o2[jp], v2);
        }
    }
}

// ---------------------------------------------------------------------------
extern "C" void kernel_launch(void* const* d_in, const int* in_sizes, int n_in,
                              void* d_out, int out_size)
{
    const float* x            = (const float*)d_in[0];          // (S,B,E)
    const float* pos_emb      = (const float*)d_in[1];          // (1,2S-1,PDIM)
    const unsigned char* kpm  = (const unsigned char*)d_in[2];  // (B,S) bool
    const float* in_proj_w    = (const float*)d_in[3];          // (544,512)
    const float* in_proj_b    = (const float*)d_in[4];          // (544,)
    const float* linear_pos_w = (const float*)d_in[5];          // (32,192)
    float* out = (float*)d_out;                                 // (H,B,S,S)

    static bool attr_set = false;
    if (!attr_set) {
        cudaFuncSetAttribute(attn_kernel,
                             cudaFuncAttributeMaxDynamicSharedMemorySize, SMEM_ATTN);
        cudaFuncSetAttribute(proj_mma_kernel,
                             cudaFuncAttributeMaxDynamicSharedMemorySize, SMEM_PROJ);
        attr_set = true;
    }

    prep_kernel<<<SPLIT_BLOCKS + PE_BLOCKS, 256>>>(x, in_proj_w, pos_emb, linear_pos_w);

    dim3 g1(9, 64);
    proj_mma_kernel<<<g1, 256, SMEM_PROJ>>>(in_proj_b);

    dim3 g3(2, 64);                          // persistent: 128 CTAs, 1/SM
    attn_kernel<<<g3, 512, SMEM_ATTN>>>(kpm, out);
}

// round 16
// speedup vs baseline: 1.0693x; 1.0693x over previous
#include <cuda_runtime.h>
#include <cuda_fp16.h>
#include <cuda_bf16.h>

#define SQ 1024
#define NB 8
#define NE 512
#define NH 8
#define QHD 32
#define PHD 4
#define PDIM 192
#define NPOS (2*SQ-1)   // 2047
#define INPROJ 544
#define MROWS (SQ*NB)   // 8192
#define K2E (NE/2)      // 256
#define LOG2E 1.4426950408889634f

typedef unsigned long long u64;
typedef unsigned int u32;

// bf16 mma m16n8k16, fp32 accumulate (in-place)
#define MMA16816(d, a0, a1, a2, a3, b0, b1) \
    asm("mma.sync.aligned.m16n8k16.row.col.f32.bf16.bf16.f32 " \
        "{%0,%1,%2,%3}, {%4,%5,%6,%7}, {%8,%9}, {%0,%1,%2,%3};" \
        : "+f"(d[0]), "+f"(d[1]), "+f"(d[2]), "+f"(d[3]) \
        : "r"(a0), "r"(a1), "r"(a2), "r"(a3), "r"(b0), "r"(b1))

#define CPA16(d, s) asm volatile("cp.async.cg.shared.global [%0], [%1], 16;" :: "r"(d), "l"(s))
#define CPA4(d, s)  asm volatile("cp.async.ca.shared.global [%0], [%1], 4;"  :: "r"(d), "l"(s))
#define CPA_COMMIT() asm volatile("cp.async.commit_group;")
#define CPA_WAITG1() asm volatile("cp.async.wait_group 1;" ::: "memory")

__device__ __forceinline__ float fast_exp2(float x)
{
    float r;
    asm("ex2.approx.f32 %0, %1;" : "=f"(r) : "f"(x));
    return r;
}

// Scratch (device globals; no allocations allowed)
__device__ __align__(16) u32  g_xh[MROWS*K2E];     // x split hi [row][k2]
__device__ __align__(16) u32  g_xl[MROWS*K2E];
__device__ __align__(16) u32  g_whT[K2E*INPROJ];   // w split hi, transposed [k2][col]
__device__ __align__(16) u32  g_wlT[K2E*INPROJ];
__device__ __align__(16) u32  g_qh[NH*NB*SQ*16];   // [hb][s][perm(d2)] bf16x2 hi (scaled log2e)
__device__ __align__(16) u32  g_ql[NH*NB*SQ*16];
__device__ __align__(16) u32  g_kh[NH*NB*SQ*16];   // [hb][s][d2] (unpermuted)
__device__ __align__(16) u32  g_kl[NH*NB*SQ*16];
__device__ __align__(16) float g_p[NH*NB*SQ*PHD];  // [hb][s][d] fp32 (scaled log2e)
__device__ __align__(16) float4 g_pe_f[NH*NPOS + 8]; // [h][n]: 4 x fp32

// v0,v1 -> hi (bf16x2: lo-half=v0), lo = residual pair
__device__ __forceinline__ void split_pair(float c0, float c1, u32& hi, u32& lo)
{
    u32 h;
    asm("cvt.rn.bf16x2.f32 %0, %1, %2;" : "=r"(h) : "f"(c1), "f"(c0));
    float f0 = __uint_as_float(h << 16);
    float f1 = __uint_as_float(h & 0xffff0000u);
    float r0 = c0 - f0, r1 = c1 - f1;
    asm("cvt.rn.bf16x2.f32 %0, %1, %2;" : "=r"(lo) : "f"(r1), "f"(r0));
    hi = h;
}

// ---------------------------------------------------------------------------
// Kernel 0 (merged, VECTORIZED): blocks [0, SPLIT_BLOCKS) split x/w 4 pairs
// per thread (MLP>=2); blocks [SPLIT_BLOCKS, +64) compute pe projection.
// ---------------------------------------------------------------------------
#define X4TOT (MROWS*K2E/4)          // 524288
#define W4TOT (INPROJ*K2E/4)         // 34816
#define SPLIT_BLOCKS ((X4TOT + W4TOT)/256)   // 2184 (exact)
#define PE_BLOCKS (8*NH)             // 64

__global__ __launch_bounds__(256) void prep_kernel(
    const float* __restrict__ x, const float* __restrict__ w,
    const float* __restrict__ pos_emb, const float* __restrict__ lw)
{
    const int blk = blockIdx.x;
    const int tid = threadIdx.x;
    if (blk < SPLIT_BLOCKS) {
        int idx4 = blk * 256 + tid;
        if (idx4 < X4TOT) {
            // x: row-contiguous, 2x float4 loads -> 4 pairs -> uint4 stores
            int row = idx4 >> 6, k2g = idx4 & 63;
            const float4* xr = (const float4*)&x[(size_t)row*NE + k2g*8];
            float4 v0 = __ldg(&xr[0]);
            float4 v1 = __ldg(&xr[1]);
            uint4 hi, lo;
            split_pair(v0.x, v0.y, hi.x, lo.x);
            split_pair(v0.z, v0.w, hi.y, lo.y);
            split_pair(v1.x, v1.y, hi.z, lo.z);
            split_pair(v1.z, v1.w, hi.w, lo.w);
            size_t off = ((size_t)row*K2E + k2g*4) >> 2;
            ((uint4*)g_xh)[off] = hi;
            ((uint4*)g_xl)[off] = lo;
        } else {
            int i = idx4 - X4TOT;
            // w: 4 cols per thread at fixed k2 (4 strided loads, MLP=4),
            // coalesced transposed uint4 store
            int k2 = i / (INPROJ/4), colq = i % (INPROJ/4);
            float2 a = *(const float2*)&w[(size_t)(colq*4+0)*NE + 2*k2];
            float2 bf = *(const float2*)&w[(size_t)(colq*4+1)*NE + 2*k2];
            float2 c = *(const float2*)&w[(size_t)(colq*4+2)*NE + 2*k2];
            float2 d = *(const float2*)&w[(size_t)(colq*4+3)*NE + 2*k2];
            uint4 hi, lo;
            split_pair(a.x, a.y, hi.x, lo.x);
            split_pair(bf.x, bf.y, hi.y, lo.y);
            split_pair(c.x, c.y, hi.z, lo.z);
            split_pair(d.x, d.y, hi.w, lo.w);
            size_t off = ((size_t)k2*INPROJ + colq*4) >> 2;
            ((uint4*)g_whT)[off] = hi;
            ((uint4*)g_wlT)[off] = lo;
        }
        return;
    }
    // ---- pe path ----
    __shared__ float ws[4][193];
    const int pb = blk - SPLIT_BLOCKS;
    const int h = pb & 7;
    const int nblk = pb >> 3;
    for (int i = tid; i < 4*PDIM; i += 256) {
        int o = i / PDIM, p = i % PDIM;
        ws[o][p] = lw[(h*4+o)*PDIM + p];
    }
    __syncthreads();
    int n = nblk * 256 + tid;
    if (n >= NPOS) return;
    float a0 = 0.f, a1 = 0.f, a2 = 0.f, a3 = 0.f;
    const float4* pr = (const float4*)&pos_emb[(size_t)n*PDIM];
#pragma unroll 4
    for (int p4 = 0; p4 < PDIM/4; ++p4) {
        float4 pv = __ldg(&pr[p4]);
        int p = p4*4;
        a0 = fmaf(pv.x, ws[0][p+0], a0); a1 = fmaf(pv.x, ws[1][p+0], a1);
        a2 = fmaf(pv.x, ws[2][p+0], a2); a3 = fmaf(pv.x, ws[3][p+0], a3);
        a0 = fmaf(pv.y, ws[0][p+1], a0); a1 = fmaf(pv.y, ws[1][p+1], a1);
        a2 = fmaf(pv.y, ws[2][p+1], a2); a3 = fmaf(pv.y, ws[3][p+1], a3);
        a0 = fmaf(pv.z, ws[0][p+2], a0); a1 = fmaf(pv.z, ws[1][p+2], a1);
        a2 = fmaf(pv.z, ws[2][p+2], a2); a3 = fmaf(pv.z, ws[3][p+2], a3);
        a0 = fmaf(pv.w, ws[0][p+3], a0); a1 = fmaf(pv.w, ws[1][p+3], a1);
        a2 = fmaf(pv.w, ws[2][p+3], a2); a3 = fmaf(pv.w, ws[3][p+3], a3);
    }
    g_pe_f[h*NPOS + n] = make_float4(a0, a1, a2, a3);
}

// ---------------------------------------------------------------------------
// Kernel 1: proj = x @ W^T + b via split-bf16 mma.sync (hh+hl+lh).
// q epilogue writes PERMUTED d2 position; k unpermuted; q,p scaled by log2e.
// ---------------------------------------------------------------------------
#define PA 20
#define PB 72
#define ST_A  2560
#define ST_B  1152
#define ST_SZ (2*ST_A + 2*ST_B)
#define SMEM_PROJ (2*ST_SZ*4)

__global__ __launch_bounds__(256, 2) void proj_mma_kernel(
    const float* __restrict__ bias)
{
    extern __shared__ u32 sm[];
    const int tid = threadIdx.x;
    const int w = tid >> 5, lane = tid & 31;
    const int g = lane >> 2, tig = lane & 3;
    const int warp_m = w >> 1, warp_n = w & 1;
    const int m0 = blockIdx.y * 128;
    const int n0 = blockIdx.x * 64;

    const int a_row = tid >> 1, a_half = tid & 1;
    const uint4* xh4 = (const uint4*)g_xh;
    const uint4* xl4 = (const uint4*)g_xl;
    const size_t a_base = ((size_t)(m0 + a_row)*K2E) >> 2;

    const int b_k2l = tid >> 4, b_colq = tid & 15;
    const bool b_valid = (n0 + b_colq*4) < INPROJ;

    uint4 pa_h0, pa_h1, pa_l0, pa_l1, pb_h, pb_l;
    {
        size_t ai = a_base + a_half*2;
        pa_h0 = __ldg(&xh4[ai]);   pa_h1 = __ldg(&xh4[ai+1]);
        pa_l0 = __ldg(&xl4[ai]);   pa_l1 = __ldg(&xl4[ai+1]);
        if (b_valid) {
            size_t bi = ((size_t)b_k2l*INPROJ + n0 + b_colq*4) >> 2;
            pb_h = __ldg(&((const uint4*)g_whT)[bi]);
            pb_l = __ldg(&((const uint4*)g_wlT)[bi]);
        } else {
            pb_h = make_uint4(0,0,0,0); pb_l = pb_h;
        }
    }

    float acc[2][4][4];
#pragma unroll
    for (int mt = 0; mt < 2; ++mt)
#pragma unroll
        for (int nt = 0; nt < 4; ++nt)
#pragma unroll
            for (int i = 0; i < 4; ++i) acc[mt][nt][i] = 0.f;

    for (int kc = 0; kc < 16; ++kc) {
        const int s = kc & 1;
        u32* Ah = sm + s*ST_SZ;
        u32* Al = Ah + ST_A;
        u32* Bh = Al + ST_A;
        u32* Bl = Bh + ST_B;
        *(uint4*)&Ah[a_row*PA + a_half*8]     = pa_h0;
        *(uint4*)&Ah[a_row*PA + a_half*8 + 4] = pa_h1;
        *(uint4*)&Al[a_row*PA + a_half*8]     = pa_l0;
        *(uint4*)&Al[a_row*PA + a_half*8 + 4] = pa_l1;
        *(uint4*)&Bh[b_k2l*PB + b_colq*4] = pb_h;
        *(uint4*)&Bl[b_k2l*PB + b_colq*4] = pb_l;
        __syncthreads();
        if (kc < 15) {
            size_t ai = a_base + (kc+1)*4 + a_half*2;
            pa_h0 = __ldg(&xh4[ai]);   pa_h1 = __ldg(&xh4[ai+1]);
            pa_l0 = __ldg(&xl4[ai]);   pa_l1 = __ldg(&xl4[ai+1]);
            if (b_valid) {
                size_t bi = ((size_t)((kc+1)*16 + b_k2l)*INPROJ + n0 + b_colq*4) >> 2;
                pb_h = __ldg(&((const uint4*)g_whT)[bi]);
                pb_l = __ldg(&((const uint4*)g_wlT)[bi]);
            }
        }
#pragma unroll
        for (int ks = 0; ks < 2; ++ks) {
            const int kb = ks*8;
            u32 ah[2][4], al[2][4];
#pragma unroll
            for (int mt = 0; mt < 2; ++mt) {
                int r1 = (warp_m*32 + mt*16 + g) * PA;
                int r2 = r1 + 8*PA;
                ah[mt][0] = Ah[r1 + kb + tig];
                ah[mt][1] = Ah[r2 + kb + tig];
                ah[mt][2] = Ah[r1 + kb + 4 + tig];
                ah[mt][3] = Ah[r2 + kb + 4 + tig];
                al[mt][0] = Al[r1 + kb + tig];
                al[mt][1] = Al[r2 + kb + tig];
                al[mt][2] = Al[r1 + kb + 4 + tig];
                al[mt][3] = Al[r2 + kb + 4 + tig];
            }
#pragma unroll
            for (int nt = 0; nt < 4; ++nt) {
                int col = warp_n*32 + nt*8 + g;
                u32 bh0 = Bh[(kb + tig)*PB + col];
                u32 bh1 = Bh[(kb + 4 + tig)*PB + col];
                u32 bl0 = Bl[(kb + tig)*PB + col];
                u32 bl1 = Bl[(kb + 4 + tig)*PB + col];
#pragma unroll
                for (int mt = 0; mt < 2; ++mt) {
                    MMA16816(acc[mt][nt], ah[mt][0], ah[mt][1], ah[mt][2], ah[mt][3], bh0, bh1);
                    MMA16816(acc[mt][nt], ah[mt][0], ah[mt][1], ah[mt][2], ah[mt][3], bl0, bl1);
                    MMA16816(acc[mt][nt], al[mt][0], al[mt][1], al[mt][2], al[mt][3], bh0, bh1);
                }
            }
        }
        __syncthreads();
    }

#pragma unroll
    for (int nt = 0; nt < 4; ++nt) {
        const int n = n0 + warp_n*32 + nt*8 + 2*tig;
        if (n >= INPROJ) continue;
        const float b0 = __ldg(&bias[n]);
        const float b1 = __ldg(&bias[n+1]);
#pragma unroll
        for (int mt = 0; mt < 2; ++mt) {
#pragma unroll
            for (int rr = 0; rr < 2; ++rr) {
                const int m = m0 + warp_m*32 + mt*16 + g + rr*8;
                const int srow = m >> 3, bb = m & 7;
                float c0 = acc[mt][nt][2*rr]     + b0;
                float c1 = acc[mt][nt][2*rr + 1] + b1;
                if (n < 512) {
                    int nn = n & 255;
                    int h = nn >> 5, d2 = (nn & 31) >> 1;
                    u32 hi, lo;
                    if (n < 256) {
                        c0 *= LOG2E; c1 *= LOG2E;
                        split_pair(c0, c1, hi, lo);
                        int pos = (d2 & 3)*4 + (d2 >> 2);   // permuted (q only)
                        size_t off = (((size_t)(h*8+bb))*SQ + srow)*16 + pos;
                        g_qh[off] = hi; g_ql[off] = lo;
                    } else {
                        split_pair(c0, c1, hi, lo);
                        size_t off = (((size_t)(h*8+bb))*SQ + srow)*16 + d2;
                        g_kh[off] = hi; g_kl[off] = lo;
                    }
                } else {
                    int n3 = n - 512;
                    int h = n3 >> 2, d = n3 & 3;
                    size_t off = (((size_t)(h*8+bb))*SQ + srow)*PHD + d;
                    g_p[off]   = c0 * LOG2E;
                    g_p[off+1] = c1 * LOG2E;
                }
            }
        }
    }
}

// ---------------------------------------------------------------------------
// Kernel 2: persistent attention — EXACT R12 body (best verified: 144.9us,
// rel_err 9.5e-6, regs 126).
// ---------------------------------------------------------------------------
#define KJ_P 20
#define OFF_KB   0                          // 2 * 1024*20*4 = 163840
#define KB_LO    (1024*KJ_P)                // u32 offset of lo array
#define OFF_PE0  163840                     // 8 pairs * 160 float4 = 20480
#define OFF_PE1  184320                     // 20480
#define OFF_RED  204800                     // 32*8*4 = 1024
#define OFF_INV  205824                     // 128
#define OFF_MASK 205952                     // 8 pairs * 128 = 1024
#define SMEM_ATTN 206976

struct BFrag { u32 h0, h1, h2, h3, l0, l1, l2, l3; };

__device__ __forceinline__ void ld_bfrag(BFrag& f, const u32* kb2h, const u32* kb2l,
                                         int jc, int tig)
{
    const u32* kr = kb2h + jc*KJ_P;
    const u32* lr = kb2l + jc*KJ_P;
    f.h0 = kr[tig];     f.h1 = kr[4 + tig];
    f.h2 = kr[8 + tig]; f.h3 = kr[12 + tig];
    f.l0 = lr[tig];     f.l1 = lr[4 + tig];
    f.l2 = lr[8 + tig]; f.l3 = lr[12 + tig];
}

__device__ __forceinline__ float dot4acc(float4 p, float4 e, float a)
{
    return fmaf(p.x, e.x, fmaf(p.y, e.y, fmaf(p.z, e.z, fmaf(p.w, e.w, a))));
}

__global__ __launch_bounds__(512, 1) void attn_kernel(
    const unsigned char* __restrict__ kpm, float* __restrict__ out)
{
    extern __shared__ char smraw[];
    u32*   kb2h  = (u32*)(smraw + OFF_KB);       // [1024 j][20] (16 k2 used)
    u32*   kb2l  = kb2h + KB_LO;
    float* red_s = (float*)(smraw + OFF_RED);    // [32][8]
    float* inv_s = (float*)(smraw + OFF_INV);    // [32]
    unsigned char* mask_l = (unsigned char*)(smraw + OFF_MASK); // [8][128]
    const u32 smb = (u32)__cvta_generic_to_shared(smraw);

    const int tid = threadIdx.x;
    const int w = tid >> 5, lane = tid & 31;
    const int g = lane >> 2, tig = lane & 3;
    const int pairid = w >> 1;
    const int jstart = pairid * 128;
    const int hb = blockIdx.y;
    const int h = hb >> 3, b = hb & 7;
    const int qbase = blockIdx.x * 512;
    const size_t hbSQ = (size_t)hb * SQ;
    const int tpair = (w & 1)*32 + lane;

    const int rbase = (w & 1) * 16;
    const int r1 = rbase + g, r2 = r1 + 8;

    // ---- prologue: K panel (once), mask (once), pe(0) ----
    {
        const u32* ksrc = ((w & 1) ? g_kl : g_kh) + (hbSQ + jstart)*16;
        const u32 kdst = smb + OFF_KB + (w & 1)*(KB_LO*4) + jstart*KJ_P*4;
#pragma unroll
        for (int i = 0; i < 16; ++i) {
            int lin = i*32 + lane;
            int jl = lin >> 2, seg = lin & 3;
            CPA16(kdst + (jl*KJ_P + seg*4)*4, ksrc + jl*16 + seg*4);
        }
        if (tpair < 32)
            CPA4(smb + OFF_MASK + pairid*128 + tpair*4,
                 kpm + (size_t)b*SQ + jstart + tpair*4);
        const float4* pesrc = g_pe_f + h*NPOS + (992 - qbase) + jstart;
        const u32 pedst = smb + OFF_PE0 + pairid*160*16;
#pragma unroll
        for (int it = 0; it < 3; ++it) {
            int i = tpair + it*64;
            if (i < 160) CPA16(pedst + i*16, pesrc + i);
        }
        CPA_COMMIT();
    }

    // A(0)/p(0) prefetch (register, per-warp)
    u32 ah[8], al[8];
    float4 pv1, pv2;
    {
        const uint4* qa = (const uint4*)(g_qh + (hbSQ + qbase + r1)*16);
        const uint4* qb = (const uint4*)(g_qh + (hbSQ + qbase + r2)*16);
        const uint4* la = (const uint4*)(g_ql + (hbSQ + qbase + r1)*16);
        const uint4* lb = (const uint4*)(g_ql + (hbSQ + qbase + r2)*16);
        uint4 v1 = __ldg(&qa[tig]);
        uint4 v2 = __ldg(&qb[tig]);
        uint4 u1 = __ldg(&la[tig]);
        uint4 u2 = __ldg(&lb[tig]);
        ah[0] = v1.x; ah[1] = v2.x; ah[2] = v1.y; ah[3] = v2.y;
        ah[4] = v1.z; ah[5] = v2.z; ah[6] = v1.w; ah[7] = v2.w;
        al[0] = u1.x; al[1] = u2.x; al[2] = u1.y; al[3] = u2.y;
        al[4] = u1.z; al[5] = u2.z; al[6] = u1.w; al[7] = u2.w;
        pv1 = *(const float4*)(g_p + (hbSQ + qbase + r1)*PHD);
        pv2 = *(const float4*)(g_p + (hbSQ + qbase + r2)*PHD);
    }

    const unsigned char* mkb = mask_l + pairid*128;

#pragma unroll 1
    for (int qi = 0; qi < 16; ++qi) {
        const int q0 = qbase + qi*32;
        // issue pe(qi+1) into stage (qi+1)&1
        if (qi < 15) {
            const float4* pesrc = g_pe_f + h*NPOS + (992 - (q0 + 32)) + jstart;
            const u32 pedst = smb + (((qi+1) & 1) ? OFF_PE1 : OFF_PE0) + pairid*160*16;
#pragma unroll
            for (int it = 0; it < 3; ++it) {
                int i = tpair + it*64;
                if (i < 160) CPA16(pedst + i*16, pesrc + i);
            }
        }
        CPA_COMMIT();
        CPA_WAITG1();              // pe(qi) (and K/mask on qi==0) complete
        asm volatile("bar.sync %0, 64;" :: "r"(1 + pairid) : "memory");

        const float4* peb4 = (const float4*)(smraw + ((qi & 1) ? OFF_PE1 : OFF_PE0))
                             + pairid*160;

        float acc[16][4];
#pragma unroll
        for (int t = 0; t < 16; ++t)
#pragma unroll
            for (int i = 0; i < 4; ++i) acc[t][i] = 0.f;

        float s1 = 0.f, s2 = 0.f;

        // pe carry init (row2 of tile e uses row1 loads of tile e-1)
        const int idx0 = 2*tig + 31 - r1;     // idx1 at e=0; >= 8 always
        float4 c11 = peb4[idx0 - 8];
        float4 c12 = peb4[idx0 - 7];

        // ---- fused pipelined loop: MMA(t) overlaps epilogue(t-1) ----
        BFrag bf;
        ld_bfrag(bf, kb2h, kb2l, jstart + g, tig);
#pragma unroll
        for (int t = 0; t < 16; ++t) {
            BFrag cur = bf;
            if (t < 15) ld_bfrag(bf, kb2h, kb2l, jstart + 8*(t+1) + g, tig);
            MMA16816(acc[t], ah[0], ah[1], ah[2], ah[3], cur.h0, cur.h1);
            MMA16816(acc[t], ah[4], ah[5], ah[6], ah[7], cur.h2, cur.h3);
            MMA16816(acc[t], ah[0], ah[1], ah[2], ah[3], cur.l0, cur.l1);
            MMA16816(acc[t], ah[4], ah[5], ah[6], ah[7], cur.l2, cur.l3);
            MMA16816(acc[t], al[0], al[1], al[2], al[3], cur.h0, cur.h1);
            MMA16816(acc[t], al[4], al[5], al[6], al[7], cur.h2, cur.h3);

            if (t > 0) {
                const int e = t - 1;
                const int jl0 = 8*e + 2*tig;
                const int idx1 = jl0 + 31 - r1;
                float4 e11 = peb4[idx1];
                float4 e12 = peb4[idx1 + 1];
                const bool m0 = mkb[jl0] != 0;
                const bool m1 = mkb[jl0 + 1] != 0;
                float e0 = m0 ? 0.f : fast_exp2(dot4acc(pv1, e11, acc[e][0]));
                float e1 = m1 ? 0.f : fast_exp2(dot4acc(pv1, e12, acc[e][1]));
                float e2 = m0 ? 0.f : fast_exp2(dot4acc(pv2, c11, acc[e][2]));
                float e3 = m1 ? 0.f : fast_exp2(dot4acc(pv2, c12, acc[e][3]));
                c11 = e11; c12 = e12;
                acc[e][0] = e0; acc[e][1] = e1; acc[e][2] = e2; acc[e][3] = e3;
                s1 += e0 + e1;
                s2 += e2 + e3;
            }
        }

        // ---- prefetch A/p for qi+1 (hidden behind tail+reduction+stores) ----
        if (qi < 15) {
            const int q0n = q0 + 32;
            const uint4* qa = (const uint4*)(g_qh + (hbSQ + q0n + r1)*16);
            const uint4* qb = (const uint4*)(g_qh + (hbSQ + q0n + r2)*16);
            const uint4* la = (const uint4*)(g_ql + (hbSQ + q0n + r1)*16);
            const uint4* lb = (const uint4*)(g_ql + (hbSQ + q0n + r2)*16);
            uint4 v1 = __ldg(&qa[tig]);
            uint4 v2 = __ldg(&qb[tig]);
            uint4 u1 = __ldg(&la[tig]);
            uint4 u2 = __ldg(&lb[tig]);
            ah[0] = v1.x; ah[1] = v2.x; ah[2] = v1.y; ah[3] = v2.y;
            ah[4] = v1.z; ah[5] = v2.z; ah[6] = v1.w; ah[7] = v2.w;
            al[0] = u1.x; al[1] = u2.x; al[2] = u1.y; al[3] = u2.y;
            al[4] = u1.z; al[5] = u2.z; al[6] = u1.w; al[7] = u2.w;
        }

        {   // epilogue tile 15
            const int e = 15;
            const int jl0 = 8*e + 2*tig;
            const int idx1 = jl0 + 31 - r1;
            float4 e11 = peb4[idx1];
            float4 e12 = peb4[idx1 + 1];
            const bool m0 = mkb[jl0] != 0;
            const bool m1 = mkb[jl0 + 1] != 0;
            float e0 = m0 ? 0.f : fast_exp2(dot4acc(pv1, e11, acc[e][0]));
            float e1 = m1 ? 0.f : fast_exp2(dot4acc(pv1, e12, acc[e][1]));
            float e2 = m0 ? 0.f : fast_exp2(dot4acc(pv2, c11, acc[e][2]));
            float e3 = m1 ? 0.f : fast_exp2(dot4acc(pv2, c12, acc[e][3]));
            acc[e][0] = e0; acc[e][1] = e1; acc[e][2] = e2; acc[e][3] = e3;
            s1 += e0 + e1;
            s2 += e2 + e3;
        }

        if (qi < 15) {
            const int q0n = q0 + 32;
            pv1 = *(const float4*)(g_p + (hbSQ + q0n + r1)*PHD);
            pv2 = *(const float4*)(g_p + (hbSQ + q0n + r2)*PHD);
        }

        s1 += __shfl_xor_sync(0xffffffffu, s1, 1);
        s1 += __shfl_xor_sync(0xffffffffu, s1, 2);
        s2 += __shfl_xor_sync(0xffffffffu, s2, 1);
        s2 += __shfl_xor_sync(0xffffffffu, s2, 2);
        if (tig == 0) {
            red_s[r1*8 + pairid] = s1;
            red_s[r2*8 + pairid] = s2;
        }
        __syncthreads();
        if (tid < 32) {
            float s = red_s[tid*8];
#pragma unroll
            for (int i = 1; i < 8; ++i) s += red_s[tid*8 + i];
            inv_s[tid] = 1.0f / s;
        }
        __syncthreads();

        // ---- normalize + streaming float2 stores ----
        const float i1 = inv_s[r1], i2 = inv_s[r2];
        float2* o1 = (float2*)(out + (hbSQ + q0 + r1)*SQ);
        float2* o2 = (float2*)(out + (hbSQ + q0 + r2)*SQ);
#pragma unroll
        for (int t = 0; t < 16; ++t) {
            const int jp = (jstart + 8*t + 2*tig) >> 1;
            float2 v1 = make_float2(acc[t][0] * i1, acc[t][1] * i1);
            float2 v2 = make_float2(acc[t][2] * i2, acc[t][3] * i2);
            __stcs(&o1[jp], v1);
            __stcs(&o2[jp], v2);
        }
    }
}

// ---------------------------------------------------------------------------
extern "C" void kernel_launch(void* const* d_in, const int* in_sizes, int n_in,
                              void* d_out, int out_size)
{
    const float* x            = (const float*)d_in[0];          // (S,B,E)
    const float* pos_emb      = (const float*)d_in[1];          // (1,2S-1,PDIM)
    const unsigned char* kpm  = (const unsigned char*)d_in[2];  // (B,S) bool
    const float* in_proj_w    = (const float*)d_in[3];          // (544,512)
    const float* in_proj_b    = (const float*)d_in[4];          // (544,)
    const float* linear_pos_w = (const float*)d_in[5];          // (32,192)
    float* out = (float*)d_out;                                 // (H,B,S,S)

    static bool attr_set = false;
    if (!attr_set) {
        cudaFuncSetAttribute(attn_kernel,
                             cudaFuncAttributeMaxDynamicSharedMemorySize, SMEM_ATTN);
        cudaFuncSetAttribute(proj_mma_kernel,
                             cudaFuncAttributeMaxDynamicSharedMemorySize, SMEM_PROJ);
        attr_set = true;
    }

    prep_kernel<<<SPLIT_BLOCKS + PE_BLOCKS, 256>>>(x, in_proj_w, pos_emb, linear_pos_w);

    dim3 g1(9, 64);
    proj_mma_kernel<<<g1, 256, SMEM_PROJ>>>(in_proj_b);

    dim3 g3(2, 64);                          // persistent: 128 CTAs, 1/SM
    attn_kernel<<<g3, 512, SMEM_ATTN>>>(kpm, out);
}

// round 17
// speedup vs baseline: 1.0985x; 1.0273x over previous
#include <cuda_runtime.h>
#include <cuda_fp16.h>
#include <cuda_bf16.h>

#define SQ 1024
#define NB 8
#define NE 512
#define NH 8
#define QHD 32
#define PHD 4
#define PDIM 192
#define NPOS (2*SQ-1)   // 2047
#define INPROJ 544
#define MROWS (SQ*NB)   // 8192
#define K2E (NE/2)      // 256
#define LOG2E 1.4426950408889634f

typedef unsigned long long u64;
typedef unsigned int u32;

// bf16 mma m16n8k16, fp32 accumulate (in-place)
#define MMA16816(d, a0, a1, a2, a3, b0, b1) \
    asm("mma.sync.aligned.m16n8k16.row.col.f32.bf16.bf16.f32 " \
        "{%0,%1,%2,%3}, {%4,%5,%6,%7}, {%8,%9}, {%0,%1,%2,%3};" \
        : "+f"(d[0]), "+f"(d[1]), "+f"(d[2]), "+f"(d[3]) \
        : "r"(a0), "r"(a1), "r"(a2), "r"(a3), "r"(b0), "r"(b1))

#define CPA16(d, s) asm volatile("cp.async.cg.shared.global [%0], [%1], 16;" :: "r"(d), "l"(s))
#define CPA4(d, s)  asm volatile("cp.async.ca.shared.global [%0], [%1], 4;"  :: "r"(d), "l"(s))
#define CPA_COMMIT() asm volatile("cp.async.commit_group;")
#define CPA_WAITG1() asm volatile("cp.async.wait_group 1;" ::: "memory")

__device__ __forceinline__ float fast_exp2(float x)
{
    float r;
    asm("ex2.approx.f32 %0, %1;" : "=f"(r) : "f"(x));
    return r;
}

// Scratch (device globals; no allocations allowed)
__device__ __align__(16) u32  g_whT[K2E*INPROJ];   // w split hi, transposed [k2][col]
__device__ __align__(16) u32  g_wlT[K2E*INPROJ];
__device__ __align__(16) u32  g_qh[NH*NB*SQ*16];   // [hb][s][perm(d2)] bf16x2 hi (scaled log2e)
__device__ __align__(16) u32  g_ql[NH*NB*SQ*16];
__device__ __align__(16) u32  g_kh[NH*NB*SQ*16];   // [hb][s][d2] (unpermuted)
__device__ __align__(16) u32  g_kl[NH*NB*SQ*16];
__device__ __align__(16) float g_p[NH*NB*SQ*PHD];  // [hb][s][d] fp32 (scaled log2e)
__device__ __align__(16) float4 g_pe_f[NH*NPOS + 8]; // [h][n]: 4 x fp32

// v0,v1 -> hi (bf16x2: lo-half=v0), lo = residual pair
__device__ __forceinline__ void split_pair(float c0, float c1, u32& hi, u32& lo)
{
    u32 h;
    asm("cvt.rn.bf16x2.f32 %0, %1, %2;" : "=r"(h) : "f"(c1), "f"(c0));
    float f0 = __uint_as_float(h << 16);
    float f1 = __uint_as_float(h & 0xffff0000u);
    float r0 = c0 - f0, r1 = c1 - f1;
    asm("cvt.rn.bf16x2.f32 %0, %1, %2;" : "=r"(lo) : "f"(r1), "f"(r0));
    hi = h;
}

// ---------------------------------------------------------------------------
// Kernel 0 (small): blocks [0, WSPLIT_BLOCKS) split+transpose w;
// blocks [WSPLIT_BLOCKS, +64) compute pe projection (fp32x4).
// x is split on-the-fly inside proj_mma_kernel (no x prep pass).
// ---------------------------------------------------------------------------
#define W4TOT (INPROJ*K2E/4)         // 34816
#define WSPLIT_BLOCKS (W4TOT/256)    // 136 (exact)
#define PE_BLOCKS (8*NH)             // 64

__global__ __launch_bounds__(256) void prep_kernel(
    const float* __restrict__ w,
    const float* __restrict__ pos_emb, const float* __restrict__ lw)
{
    const int blk = blockIdx.x;
    const int tid = threadIdx.x;
    if (blk < WSPLIT_BLOCKS) {
        int i = blk * 256 + tid;
        // w: 4 cols per thread at fixed k2 (4 strided loads, MLP=4),
        // coalesced transposed uint4 store
        int k2 = i / (INPROJ/4), colq = i % (INPROJ/4);
        float2 a = *(const float2*)&w[(size_t)(colq*4+0)*NE + 2*k2];
        float2 bf = *(const float2*)&w[(size_t)(colq*4+1)*NE + 2*k2];
        float2 c = *(const float2*)&w[(size_t)(colq*4+2)*NE + 2*k2];
        float2 d = *(const float2*)&w[(size_t)(colq*4+3)*NE + 2*k2];
        uint4 hi, lo;
        split_pair(a.x, a.y, hi.x, lo.x);
        split_pair(bf.x, bf.y, hi.y, lo.y);
        split_pair(c.x, c.y, hi.z, lo.z);
        split_pair(d.x, d.y, hi.w, lo.w);
        size_t off = ((size_t)k2*INPROJ + colq*4) >> 2;
        ((uint4*)g_whT)[off] = hi;
        ((uint4*)g_wlT)[off] = lo;
        return;
    }
    // ---- pe path ----
    __shared__ float ws[4][193];
    const int pb = blk - WSPLIT_BLOCKS;
    const int h = pb & 7;
    const int nblk = pb >> 3;
    for (int i = tid; i < 4*PDIM; i += 256) {
        int o = i / PDIM, p = i % PDIM;
        ws[o][p] = lw[(h*4+o)*PDIM + p];
    }
    __syncthreads();
    int n = nblk * 256 + tid;
    if (n >= NPOS) return;
    float a0 = 0.f, a1 = 0.f, a2 = 0.f, a3 = 0.f;
    const float4* pr = (const float4*)&pos_emb[(size_t)n*PDIM];
#pragma unroll 4
    for (int p4 = 0; p4 < PDIM/4; ++p4) {
        float4 pv = __ldg(&pr[p4]);
        int p = p4*4;
        a0 = fmaf(pv.x, ws[0][p+0], a0); a1 = fmaf(pv.x, ws[1][p+0], a1);
        a2 = fmaf(pv.x, ws[2][p+0], a2); a3 = fmaf(pv.x, ws[3][p+0], a3);
        a0 = fmaf(pv.y, ws[0][p+1], a0); a1 = fmaf(pv.y, ws[1][p+1], a1);
        a2 = fmaf(pv.y, ws[2][p+1], a2); a3 = fmaf(pv.y, ws[3][p+1], a3);
        a0 = fmaf(pv.z, ws[0][p+2], a0); a1 = fmaf(pv.z, ws[1][p+2], a1);
        a2 = fmaf(pv.z, ws[2][p+2], a2); a3 = fmaf(pv.z, ws[3][p+2], a3);
        a0 = fmaf(pv.w, ws[0][p+3], a0); a1 = fmaf(pv.w, ws[1][p+3], a1);
        a2 = fmaf(pv.w, ws[2][p+3], a2); a3 = fmaf(pv.w, ws[3][p+3], a3);
    }
    g_pe_f[h*NPOS + n] = make_float4(a0, a1, a2, a3);
}

// ---------------------------------------------------------------------------
// Kernel 1: proj = x @ W^T + b via split-bf16 mma.sync (hh+hl+lh).
// A tiles: loads x fp32 directly and splits to bf16 hi/lo in registers at
// STS time (no pre-materialized x split arrays).
// q epilogue writes PERMUTED d2 position; k unpermuted; q,p scaled by log2e.
// ---------------------------------------------------------------------------
#define PA 20
#define PB 72
#define ST_A  2560
#define ST_B  1152
#define ST_SZ (2*ST_A + 2*ST_B)
#define SMEM_PROJ (2*ST_SZ*4)

__global__ __launch_bounds__(256, 2) void proj_mma_kernel(
    const float* __restrict__ x, const float* __restrict__ bias)
{
    extern __shared__ u32 sm[];
    const int tid = threadIdx.x;
    const int w = tid >> 5, lane = tid & 31;
    const int g = lane >> 2, tig = lane & 3;
    const int warp_m = w >> 1, warp_n = w & 1;
    const int m0 = blockIdx.y * 128;
    const int n0 = blockIdx.x * 64;

    // A fill: row = tid>>1, half = tid&1; 4 float4 (fp32) per chunk per thread
    const int a_row = tid >> 1, a_half = tid & 1;
    const float4* x4 = (const float4*)x;
    const size_t a_basef = (size_t)(m0 + a_row)*(NE/4);   // float4 row base

    const int b_k2l = tid >> 4, b_colq = tid & 15;
    const bool b_valid = (n0 + b_colq*4) < INPROJ;

    float4 pa_f0, pa_f1, pa_f2, pa_f3;
    uint4 pb_h, pb_l;
    {
        size_t ai = a_basef + a_half*4;
        pa_f0 = __ldg(&x4[ai]);   pa_f1 = __ldg(&x4[ai+1]);
        pa_f2 = __ldg(&x4[ai+2]); pa_f3 = __ldg(&x4[ai+3]);
        if (b_valid) {
            size_t bi = ((size_t)b_k2l*INPROJ + n0 + b_colq*4) >> 2;
            pb_h = __ldg(&((const uint4*)g_whT)[bi]);
            pb_l = __ldg(&((const uint4*)g_wlT)[bi]);
        } else {
            pb_h = make_uint4(0,0,0,0); pb_l = pb_h;
        }
    }

    float acc[2][4][4];
#pragma unroll
    for (int mt = 0; mt < 2; ++mt)
#pragma unroll
        for (int nt = 0; nt < 4; ++nt)
#pragma unroll
            for (int i = 0; i < 4; ++i) acc[mt][nt][i] = 0.f;

    for (int kc = 0; kc < 16; ++kc) {
        const int s = kc & 1;
        u32* Ah = sm + s*ST_SZ;
        u32* Al = Ah + ST_A;
        u32* Bh = Al + ST_A;
        u32* Bl = Bh + ST_B;
        {   // split fp32 -> bf16 hi/lo at store time
            uint4 h0, h1, l0, l1;
            split_pair(pa_f0.x, pa_f0.y, h0.x, l0.x);
            split_pair(pa_f0.z, pa_f0.w, h0.y, l0.y);
            split_pair(pa_f1.x, pa_f1.y, h0.z, l0.z);
            split_pair(pa_f1.z, pa_f1.w, h0.w, l0.w);
            split_pair(pa_f2.x, pa_f2.y, h1.x, l1.x);
            split_pair(pa_f2.z, pa_f2.w, h1.y, l1.y);
            split_pair(pa_f3.x, pa_f3.y, h1.z, l1.z);
            split_pair(pa_f3.z, pa_f3.w, h1.w, l1.w);
            *(uint4*)&Ah[a_row*PA + a_half*8]     = h0;
            *(uint4*)&Ah[a_row*PA + a_half*8 + 4] = h1;
            *(uint4*)&Al[a_row*PA + a_half*8]     = l0;
            *(uint4*)&Al[a_row*PA + a_half*8 + 4] = l1;
        }
        *(uint4*)&Bh[b_k2l*PB + b_colq*4] = pb_h;
        *(uint4*)&Bl[b_k2l*PB + b_colq*4] = pb_l;
        __syncthreads();
        if (kc < 15) {
            size_t ai = a_basef + (kc+1)*8 + a_half*4;
            pa_f0 = __ldg(&x4[ai]);   pa_f1 = __ldg(&x4[ai+1]);
            pa_f2 = __ldg(&x4[ai+2]); pa_f3 = __ldg(&x4[ai+3]);
            if (b_valid) {
                size_t bi = ((size_t)((kc+1)*16 + b_k2l)*INPROJ + n0 + b_colq*4) >> 2;
                pb_h = __ldg(&((const uint4*)g_whT)[bi]);
                pb_l = __ldg(&((const uint4*)g_wlT)[bi]);
            }
        }
#pragma unroll
        for (int ks = 0; ks < 2; ++ks) {
            const int kb = ks*8;
            u32 ah[2][4], al[2][4];
#pragma unroll
            for (int mt = 0; mt < 2; ++mt) {
                int r1 = (warp_m*32 + mt*16 + g) * PA;
                int r2 = r1 + 8*PA;
                ah[mt][0] = Ah[r1 + kb + tig];
                ah[mt][1] = Ah[r2 + kb + tig];
                ah[mt][2] = Ah[r1 + kb + 4 + tig];
                ah[mt][3] = Ah[r2 + kb + 4 + tig];
                al[mt][0] = Al[r1 + kb + tig];
                al[mt][1] = Al[r2 + kb + tig];
                al[mt][2] = Al[r1 + kb + 4 + tig];
                al[mt][3] = Al[r2 + kb + 4 + tig];
            }
#pragma unroll
            for (int nt = 0; nt < 4; ++nt) {
                int col = warp_n*32 + nt*8 + g;
                u32 bh0 = Bh[(kb + tig)*PB + col];
                u32 bh1 = Bh[(kb + 4 + tig)*PB + col];
                u32 bl0 = Bl[(kb + tig)*PB + col];
                u32 bl1 = Bl[(kb + 4 + tig)*PB + col];
#pragma unroll
                for (int mt = 0; mt < 2; ++mt) {
                    MMA16816(acc[mt][nt], ah[mt][0], ah[mt][1], ah[mt][2], ah[mt][3], bh0, bh1);
                    MMA16816(acc[mt][nt], ah[mt][0], ah[mt][1], ah[mt][2], ah[mt][3], bl0, bl1);
                    MMA16816(acc[mt][nt], al[mt][0], al[mt][1], al[mt][2], al[mt][3], bh0, bh1);
                }
            }
        }
        __syncthreads();
    }

#pragma unroll
    for (int nt = 0; nt < 4; ++nt) {
        const int n = n0 + warp_n*32 + nt*8 + 2*tig;
        if (n >= INPROJ) continue;
        const float b0 = __ldg(&bias[n]);
        const float b1 = __ldg(&bias[n+1]);
#pragma unroll
        for (int mt = 0; mt < 2; ++mt) {
#pragma unroll
            for (int rr = 0; rr < 2; ++rr) {
                const int m = m0 + warp_m*32 + mt*16 + g + rr*8;
                const int srow = m >> 3, bb = m & 7;
                float c0 = acc[mt][nt][2*rr]     + b0;
                float c1 = acc[mt][nt][2*rr + 1] + b1;
                if (n < 512) {
                    int nn = n & 255;
                    int h = nn >> 5, d2 = (nn & 31) >> 1;
                    u32 hi, lo;
                    if (n < 256) {
                        c0 *= LOG2E; c1 *= LOG2E;
                        split_pair(c0, c1, hi, lo);
                        int pos = (d2 & 3)*4 + (d2 >> 2);   // permuted (q only)
                        size_t off = (((size_t)(h*8+bb))*SQ + srow)*16 + pos;
                        g_qh[off] = hi; g_ql[off] = lo;
                    } else {
                        split_pair(c0, c1, hi, lo);
                        size_t off = (((size_t)(h*8+bb))*SQ + srow)*16 + d2;
                        g_kh[off] = hi; g_kl[off] = lo;
                    }
                } else {
                    int n3 = n - 512;
                    int h = n3 >> 2, d = n3 & 3;
                    size_t off = (((size_t)(h*8+bb))*SQ + srow)*PHD + d;
                    g_p[off]   = c0 * LOG2E;
                    g_p[off+1] = c1 * LOG2E;
                }
            }
        }
    }
}

// ---------------------------------------------------------------------------
// Kernel 2: persistent attention — EXACT R12 body (best verified: 144.9us,
// rel_err 9.5e-6, regs 126).
// ---------------------------------------------------------------------------
#define KJ_P 20
#define OFF_KB   0                          // 2 * 1024*20*4 = 163840
#define KB_LO    (1024*KJ_P)                // u32 offset of lo array
#define OFF_PE0  163840                     // 8 pairs * 160 float4 = 20480
#define OFF_PE1  184320                     // 20480
#define OFF_RED  204800                     // 32*8*4 = 1024
#define OFF_INV  205824                     // 128
#define OFF_MASK 205952                     // 8 pairs * 128 = 1024
#define SMEM_ATTN 206976

struct BFrag { u32 h0, h1, h2, h3, l0, l1, l2, l3; };

__device__ __forceinline__ void ld_bfrag(BFrag& f, const u32* kb2h, const u32* kb2l,
                                         int jc, int tig)
{
    const u32* kr = kb2h + jc*KJ_P;
    const u32* lr = kb2l + jc*KJ_P;
    f.h0 = kr[tig];     f.h1 = kr[4 + tig];
    f.h2 = kr[8 + tig]; f.h3 = kr[12 + tig];
    f.l0 = lr[tig];     f.l1 = lr[4 + tig];
    f.l2 = lr[8 + tig]; f.l3 = lr[12 + tig];
}

__device__ __forceinline__ float dot4acc(float4 p, float4 e, float a)
{
    return fmaf(p.x, e.x, fmaf(p.y, e.y, fmaf(p.z, e.z, fmaf(p.w, e.w, a))));
}

__global__ __launch_bounds__(512, 1) void attn_kernel(
    const unsigned char* __restrict__ kpm, float* __restrict__ out)
{
    extern __shared__ char smraw[];
    u32*   kb2h  = (u32*)(smraw + OFF_KB);       // [1024 j][20] (16 k2 used)
    u32*   kb2l  = kb2h + KB_LO;
    float* red_s = (float*)(smraw + OFF_RED);    // [32][8]
    float* inv_s = (float*)(smraw + OFF_INV);    // [32]
    unsigned char* mask_l = (unsigned char*)(smraw + OFF_MASK); // [8][128]
    const u32 smb = (u32)__cvta_generic_to_shared(smraw);

    const int tid = threadIdx.x;
    const int w = tid >> 5, lane = tid & 31;
    const int g = lane >> 2, tig = lane & 3;
    const int pairid = w >> 1;
    const int jstart = pairid * 128;
    const int hb = blockIdx.y;
    const int h = hb >> 3, b = hb & 7;
    const int qbase = blockIdx.x * 512;
    const size_t hbSQ = (size_t)hb * SQ;
    const int tpair = (w & 1)*32 + lane;

    const int rbase = (w & 1) * 16;
    const int r1 = rbase + g, r2 = r1 + 8;

    // ---- prologue: K panel (once), mask (once), pe(0) ----
    {
        const u32* ksrc = ((w & 1) ? g_kl : g_kh) + (hbSQ + jstart)*16;
        const u32 kdst = smb + OFF_KB + (w & 1)*(KB_LO*4) + jstart*KJ_P*4;
#pragma unroll
        for (int i = 0; i < 16; ++i) {
            int lin = i*32 + lane;
            int jl = lin >> 2, seg = lin & 3;
            CPA16(kdst + (jl*KJ_P + seg*4)*4, ksrc + jl*16 + seg*4);
        }
        if (tpair < 32)
            CPA4(smb + OFF_MASK + pairid*128 + tpair*4,
                 kpm + (size_t)b*SQ + jstart + tpair*4);
        const float4* pesrc = g_pe_f + h*NPOS + (992 - qbase) + jstart;
        const u32 pedst = smb + OFF_PE0 + pairid*160*16;
#pragma unroll
        for (int it = 0; it < 3; ++it) {
            int i = tpair + it*64;
            if (i < 160) CPA16(pedst + i*16, pesrc + i);
        }
        CPA_COMMIT();
    }

    // A(0)/p(0) prefetch (register, per-warp)
    u32 ah[8], al[8];
    float4 pv1, pv2;
    {
        const uint4* qa = (const uint4*)(g_qh + (hbSQ + qbase + r1)*16);
        const uint4* qb = (const uint4*)(g_qh + (hbSQ + qbase + r2)*16);
        const uint4* la = (const uint4*)(g_ql + (hbSQ + qbase + r1)*16);
        const uint4* lb = (const uint4*)(g_ql + (hbSQ + qbase + r2)*16);
        uint4 v1 = __ldg(&qa[tig]);
        uint4 v2 = __ldg(&qb[tig]);
        uint4 u1 = __ldg(&la[tig]);
        uint4 u2 = __ldg(&lb[tig]);
        ah[0] = v1.x; ah[1] = v2.x; ah[2] = v1.y; ah[3] = v2.y;
        ah[4] = v1.z; ah[5] = v2.z; ah[6] = v1.w; ah[7] = v2.w;
        al[0] = u1.x; al[1] = u2.x; al[2] = u1.y; al[3] = u2.y;
        al[4] = u1.z; al[5] = u2.z; al[6] = u1.w; al[7] = u2.w;
        pv1 = *(const float4*)(g_p + (hbSQ + qbase + r1)*PHD);
        pv2 = *(const float4*)(g_p + (hbSQ + qbase + r2)*PHD);
    }

    const unsigned char* mkb = mask_l + pairid*128;

#pragma unroll 1
    for (int qi = 0; qi < 16; ++qi) {
        const int q0 = qbase + qi*32;
        // issue pe(qi+1) into stage (qi+1)&1
        if (qi < 15) {
            const float4* pesrc = g_pe_f + h*NPOS + (992 - (q0 + 32)) + jstart;
            const u32 pedst = smb + (((qi+1) & 1) ? OFF_PE1 : OFF_PE0) + pairid*160*16;
#pragma unroll
            for (int it = 0; it < 3; ++it) {
                int i = tpair + it*64;
                if (i < 160) CPA16(pedst + i*16, pesrc + i);
            }
        }
        CPA_COMMIT();
        CPA_WAITG1();              // pe(qi) (and K/mask on qi==0) complete
        asm volatile("bar.sync %0, 64;" :: "r"(1 + pairid) : "memory");

        const float4* peb4 = (const float4*)(smraw + ((qi & 1) ? OFF_PE1 : OFF_PE0))
                             + pairid*160;

        float acc[16][4];
#pragma unroll
        for (int t = 0; t < 16; ++t)
#pragma unroll
            for (int i = 0; i < 4; ++i) acc[t][i] = 0.f;

        float s1 = 0.f, s2 = 0.f;

        // pe carry init (row2 of tile e uses row1 loads of tile e-1)
        const int idx0 = 2*tig + 31 - r1;     // idx1 at e=0; >= 8 always
        float4 c11 = peb4[idx0 - 8];
        float4 c12 = peb4[idx0 - 7];

        // ---- fused pipelined loop: MMA(t) overlaps epilogue(t-1) ----
        BFrag bf;
        ld_bfrag(bf, kb2h, kb2l, jstart + g, tig);
#pragma unroll
        for (int t = 0; t < 16; ++t) {
            BFrag cur = bf;
            if (t < 15) ld_bfrag(bf, kb2h, kb2l, jstart + 8*(t+1) + g, tig);
            MMA16816(acc[t], ah[0], ah[1], ah[2], ah[3], cur.h0, cur.h1);
            MMA16816(acc[t], ah[4], ah[5], ah[6], ah[7], cur.h2, cur.h3);
            MMA16816(acc[t], ah[0], ah[1], ah[2], ah[3], cur.l0, cur.l1);
            MMA16816(acc[t], ah[4], ah[5], ah[6], ah[7], cur.l2, cur.l3);
            MMA16816(acc[t], al[0], al[1], al[2], al[3], cur.h0, cur.h1);
            MMA16816(acc[t], al[4], al[5], al[6], al[7], cur.h2, cur.h3);

            if (t > 0) {
                const int e = t - 1;
                const int jl0 = 8*e + 2*tig;
                const int idx1 = jl0 + 31 - r1;
                float4 e11 = peb4[idx1];
                float4 e12 = peb4[idx1 + 1];
                const bool m0 = mkb[jl0] != 0;
                const bool m1 = mkb[jl0 + 1] != 0;
                float e0 = m0 ? 0.f : fast_exp2(dot4acc(pv1, e11, acc[e][0]));
                float e1 = m1 ? 0.f : fast_exp2(dot4acc(pv1, e12, acc[e][1]));
                float e2 = m0 ? 0.f : fast_exp2(dot4acc(pv2, c11, acc[e][2]));
                float e3 = m1 ? 0.f : fast_exp2(dot4acc(pv2, c12, acc[e][3]));
                c11 = e11; c12 = e12;
                acc[e][0] = e0; acc[e][1] = e1; acc[e][2] = e2; acc[e][3] = e3;
                s1 += e0 + e1;
                s2 += e2 + e3;
            }
        }

        // ---- prefetch A/p for qi+1 (hidden behind tail+reduction+stores) ----
        if (qi < 15) {
            const int q0n = q0 + 32;
            const uint4* qa = (const uint4*)(g_qh + (hbSQ + q0n + r1)*16);
            const uint4* qb = (const uint4*)(g_qh + (hbSQ + q0n + r2)*16);
            const uint4* la = (const uint4*)(g_ql + (hbSQ + q0n + r1)*16);
            const uint4* lb = (const uint4*)(g_ql + (hbSQ + q0n + r2)*16);
            uint4 v1 = __ldg(&qa[tig]);
            uint4 v2 = __ldg(&qb[tig]);
            uint4 u1 = __ldg(&la[tig]);
            uint4 u2 = __ldg(&lb[tig]);
            ah[0] = v1.x; ah[1] = v2.x; ah[2] = v1.y; ah[3] = v2.y;
            ah[4] = v1.z; ah[5] = v2.z; ah[6] = v1.w; ah[7] = v2.w;
            al[0] = u1.x; al[1] = u2.x; al[2] = u1.y; al[3] = u2.y;
            al[4] = u1.z; al[5] = u2.z; al[6] = u1.w; al[7] = u2.w;
        }

        {   // epilogue tile 15
            const int e = 15;
            const int jl0 = 8*e + 2*tig;
            const int idx1 = jl0 + 31 - r1;
            float4 e11 = peb4[idx1];
            float4 e12 = peb4[idx1 + 1];
            const bool m0 = mkb[jl0] != 0;
            const bool m1 = mkb[jl0 + 1] != 0;
            float e0 = m0 ? 0.f : fast_exp2(dot4acc(pv1, e11, acc[e][0]));
            float e1 = m1 ? 0.f : fast_exp2(dot4acc(pv1, e12, acc[e][1]));
            float e2 = m0 ? 0.f : fast_exp2(dot4acc(pv2, c11, acc[e][2]));
            float e3 = m1 ? 0.f : fast_exp2(dot4acc(pv2, c12, acc[e][3]));
            acc[e][0] = e0; acc[e][1] = e1; acc[e][2] = e2; acc[e][3] = e3;
            s1 += e0 + e1;
            s2 += e2 + e3;
        }

        if (qi < 15) {
            const int q0n = q0 + 32;
            pv1 = *(const float4*)(g_p + (hbSQ + q0n + r1)*PHD);
            pv2 = *(const float4*)(g_p + (hbSQ + q0n + r2)*PHD);
        }

        s1 += __shfl_xor_sync(0xffffffffu, s1, 1);
        s1 += __shfl_xor_sync(0xffffffffu, s1, 2);
        s2 += __shfl_xor_sync(0xffffffffu, s2, 1);
        s2 += __shfl_xor_sync(0xffffffffu, s2, 2);
        if (tig == 0) {
            red_s[r1*8 + pairid] = s1;
            red_s[r2*8 + pairid] = s2;
        }
        __syncthreads();
        if (tid < 32) {
            float s = red_s[tid*8];
#pragma unroll
            for (int i = 1; i < 8; ++i) s += red_s[tid*8 + i];
            inv_s[tid] = 1.0f / s;
        }
        __syncthreads();

        // ---- normalize + streaming float2 stores ----
        const float i1 = inv_s[r1], i2 = inv_s[r2];
        float2* o1 = (float2*)(out + (hbSQ + q0 + r1)*SQ);
        float2* o2 = (float2*)(out + (hbSQ + q0 + r2)*SQ);
#pragma unroll
        for (int t = 0; t < 16; ++t) {
            const int jp = (jstart + 8*t + 2*tig) >> 1;
            float2 v1 = make_float2(acc[t][0] * i1, acc[t][1] * i1);
            float2 v2 = make_float2(acc[t][2] * i2, acc[t][3] * i2);
            __stcs(&o1[jp], v1);
            __stcs(&o2[jp], v2);
        }
    }
}

// ---------------------------------------------------------------------------
extern "C" void kernel_launch(void* const* d_in, const int* in_sizes, int n_in,
                              void* d_out, int out_size)
{
    const float* x            = (const float*)d_in[0];          // (S,B,E)
    const float* pos_emb      = (const float*)d_in[1];          // (1,2S-1,PDIM)
    const unsigned char* kpm  = (const unsigned char*)d_in[2];  // (B,S) bool
    const float* in_proj_w    = (const float*)d_in[3];          // (544,512)
    const float* in_proj_b    = (const float*)d_in[4];          // (544,)
    const float* linear_pos_w = (const float*)d_in[5];          // (32,192)
    float* out = (float*)d_out;                                 // (H,B,S,S)

    static bool attr_set = false;
    if (!attr_set) {
        cudaFuncSetAttribute(attn_kernel,
                             cudaFuncAttributeMaxDynamicSharedMemorySize, SMEM_ATTN);
        cudaFuncSetAttribute(proj_mma_kernel,
                             cudaFuncAttributeMaxDynamicSharedMemorySize, SMEM_PROJ);
        attr_set = true;
    }

    prep_kernel<<<WSPLIT_BLOCKS + PE_BLOCKS, 256>>>(in_proj_w, pos_emb, linear_pos_w);

    dim3 g1(9, 64);
    proj_mma_kernel<<<g1, 256, SMEM_PROJ>>>(x, in_proj_b);

    dim3 g3(2, 64);                          // persistent: 128 CTAs, 1/SM
    attn_kernel<<<g3, 512, SMEM_ATTN>>>(kpm, out);
}